// round 15
// baseline (speedup 1.0000x reference)
#include <cuda_runtime.h>
#include <cuda_bf16.h>

// PepEmbedding: out[b,h,:] = soft_threshold(emb[x[b,h],:], s[x[b,h],:])
//   soft_threshold(v,s) = sign(v)*relu(|v| - sigmoid(s))
//
// R15: gather untouched (MLP=4, 32-bit offsets — ~83% DRAM at the 956MB
// compulsory floor, stable 6 rounds). Binning = ONE kernel combining two
// individually-proven mechanisms:
//   - R12's graph-replay-safe cohort grid barrier (monotonic counter)
//   - R14's atomic range-reservation with scanned bucket bases
// Per block: smem hist -> publish totals -> barrier -> smem scan (bases) ->
// reserve (base + zero-based offset cursor) -> ranks -> direct key writes ->
// last-done-block resets state for the next graph replay.

#define ROWS        (16384 * 50)     // 819,200
#define NBUCKETS    256
#define BUCKET_SHIFT 12              // idx >> 12 -> bucket 0..244
#define NBLK        200              // 819200 / 4096
#define RPB         4096             // rows per binning block
#define VEC_PER_ROW 32               // 128 floats / float4

typedef unsigned long long ull;

// Scratch (device globals — allocation is forbidden; zero-init at load)
__device__ int bucket_total[NBUCKETS];   // summed pre-barrier, reset post
__device__ int bucket_offset[NBUCKETS];  // zero-based reservation cursors
__device__ unsigned long long bar_ctr;   // monotonic cohort barrier counter
__device__ int done_ctr;
__device__ ull sorted_key[ROWS];         // (idx << 32) | row

// -------------- fused binning: hist + barrier + scan + reserve + scatter
__global__ __launch_bounds__(1024)
void k_bin(const int4* __restrict__ x4) {
    __shared__ int h[NBUCKETS];       // block-local counts
    __shared__ int h2[NBUCKETS];      // rank counters
    __shared__ int gbase[NBUCKETS];   // final global base per bucket
    __shared__ int sc[NBUCKETS];      // scan workspace
    __shared__ int is_last;

    int t = threadIdx.x;
    if (t < NBUCKETS) { h[t] = 0; h2[t] = 0; }
    __syncthreads();

    // ---- histogram (4 rows/thread via one int4 load — sole read of x)
    int4 v = x4[blockIdx.x * 1024 + t];
    int b0 = v.x >> BUCKET_SHIFT;
    int b1 = v.y >> BUCKET_SHIFT;
    int b2 = v.z >> BUCKET_SHIFT;
    int b3 = v.w >> BUCKET_SHIFT;
    atomicAdd(&h[b0], 1);
    atomicAdd(&h[b1], 1);
    atomicAdd(&h[b2], 1);
    atomicAdd(&h[b3], 1);
    __syncthreads();

    // ---- publish totals, then grid barrier (all 200 blocks co-resident:
    //      1024 thr -> 2 blocks/SM thread-limited, capacity 296 >= 200)
    if (t < NBUCKETS && h[t]) atomicAdd(&bucket_total[t], h[t]);
    __threadfence();
    __syncthreads();
    if (t == 0) {
        unsigned long long arrive = atomicAdd(&bar_ctr, 1ull) + 1ull;
        unsigned long long target = ((arrive + (NBLK - 1)) / NBLK) * NBLK;
        while (atomicAdd(&bar_ctr, 0ull) < target)   // cohort, no reset needed
            __nanosleep(64);
    }
    __syncthreads();
    __threadfence();                  // acquire peers' total updates

    // ---- bucket bases: 256-wide exclusive scan of totals (in smem, cheap)
    int tot = 0;
    if (t < NBUCKETS) { tot = bucket_total[t]; sc[t] = tot; }
    __syncthreads();
    #pragma unroll
    for (int off = 1; off < NBUCKETS; off <<= 1) {
        int u = (t < NBUCKETS && t >= off) ? sc[t - off] : 0;
        __syncthreads();
        if (t < NBUCKETS) sc[t] += u;
        __syncthreads();
    }

    // ---- reserve a contiguous run per non-empty bucket: base + offset cursor
    if (t < NBUCKETS) {
        int c = h[t];
        if (c > 0) gbase[t] = (sc[t] - tot) + atomicAdd(&bucket_offset[t], c);
    }
    __syncthreads();

    // ---- rank + direct write into reserved runs (avg 16 keys = 128B runs)
    unsigned r = (unsigned)(blockIdx.x * RPB + 4 * t);
    int lr0 = atomicAdd(&h2[b0], 1);
    sorted_key[gbase[b0] + lr0] = ((ull)(unsigned)v.x << 32) | (r + 0u);
    int lr1 = atomicAdd(&h2[b1], 1);
    sorted_key[gbase[b1] + lr1] = ((ull)(unsigned)v.y << 32) | (r + 1u);
    int lr2 = atomicAdd(&h2[b2], 1);
    sorted_key[gbase[b2] + lr2] = ((ull)(unsigned)v.z << 32) | (r + 2u);
    int lr3 = atomicAdd(&h2[b3], 1);
    sorted_key[gbase[b3] + lr3] = ((ull)(unsigned)v.w << 32) | (r + 3u);

    // ---- replay-safe state reset by the last block to finish
    __syncthreads();                  // this block's reservations+writes done
    if (t == 0) {
        __threadfence();
        is_last = (atomicAdd(&done_ctr, 1) == NBLK - 1) ? 1 : 0;
    }
    __syncthreads();
    if (is_last) {                    // all blocks have reserved & incremented
        if (t < NBUCKETS) { bucket_total[t] = 0; bucket_offset[t] = 0; }
        if (t == 0) done_ctr = 0;     // graph replay serializes after kernel
    }
}

// ---------------------------------------------------------------- gather
__device__ __forceinline__ float soft_thresh(float v, float sv) {
    float t = __fdividef(1.0f, 1.0f + __expf(-sv));
    float m = fmaxf(fabsf(v) - t, 0.0f);
    return copysignf(m, v);
}

__device__ __forceinline__ float4 soft_thresh4(float4 v, float4 t) {
    float4 o;
    o.x = soft_thresh(v.x, t.x);
    o.y = soft_thresh(v.y, t.y);
    o.z = soft_thresh(v.z, t.z);
    o.w = soft_thresh(v.w, t.w);
    return o;
}

__global__ __launch_bounds__(256, 8)
void k_gather(const float4* __restrict__ emb,
              const float4* __restrict__ s,
              float4* __restrict__ out) {
    // one warp = TWO consecutive sorted rows -> 4 independent loads per thread
    unsigned gid  = blockIdx.x * 256u + threadIdx.x;
    unsigned warp = gid >> 5;
    unsigned comp = gid & 31u;

    ulonglong2 kk = __ldg((const ulonglong2*)&sorted_key[warp * 2]); // uniform
    unsigned row0 = (unsigned)(kk.x & 0xffffffffu);
    unsigned idx0 = (unsigned)(kk.x >> 32);
    unsigned row1 = (unsigned)(kk.y & 0xffffffffu);
    unsigned idx1 = (unsigned)(kk.y >> 32);

    unsigned off0 = idx0 * (unsigned)VEC_PER_ROW + comp;
    unsigned off1 = idx1 * (unsigned)VEC_PER_ROW + comp;

    // 4 independent 16B loads in flight (MLP=4 — measured sweet spot)
    float4 v0 = __ldg(&emb[off0]);
    float4 t0 = __ldg(&s[off0]);
    float4 v1 = __ldg(&emb[off1]);
    float4 t1 = __ldg(&s[off1]);

    __stcs(&out[row0 * (unsigned)VEC_PER_ROW + comp], soft_thresh4(v0, t0));
    __stcs(&out[row1 * (unsigned)VEC_PER_ROW + comp], soft_thresh4(v1, t1));
}

// ---------------------------------------------------------------- launch
extern "C" void kernel_launch(void* const* d_in, const int* in_sizes, int n_in,
                              void* d_out, int out_size) {
    const int4*   x4  = (const int4*)d_in[0];
    const float4* emb = (const float4*)d_in[1];
    const float4* s   = (const float4*)d_in[2];
    float4*       out = (float4*)d_out;

    k_bin   <<<NBLK, 1024>>>(x4);
    k_gather<<<ROWS / 16, 256>>>(emb, s, out);
}

// round 16
// speedup vs baseline: 1.0240x; 1.0240x over previous
#include <cuda_runtime.h>
#include <cuda_bf16.h>

// PepEmbedding: out[b,h,:] = soft_threshold(emb[x[b,h],:], s[x[b,h],:])
//   soft_threshold(v,s) = sign(v)*relu(|v| - sigmoid(s))
//
// R16: gather untouched (MLP=4, 32-bit offsets — ~84% DRAM at the 956MB
// compulsory floor, stable 6 rounds). Binning = R14's passing reservation
// chain with 64 buckets instead of 256: the L2-reuse window per bucket grows
// to 16MB (still << 126MB L2, reuse preserved) while ALL bookkeeping shrinks
// 4x — scans, reservation atomics, and scatter runs become 512B contiguous
// (fully-dirty 32B sectors, no staging needed).

#define ROWS        (16384 * 50)     // 819,200
#define NBUCKETS    64
#define BUCKET_SHIFT 14              // idx >> 14 -> bucket 0..61
#define NBLK        200              // 819200 / 4096
#define RPB         4096             // rows per binning block
#define VEC_PER_ROW 32               // 128 floats / float4

typedef unsigned long long ull;

// Scratch (device globals — allocation is forbidden; zero-init at load)
__device__ int bucket_total[NBUCKETS];   // summed by k_hist, reset by k_scan
__device__ int bucket_cursor[NBUCKETS];  // set to bases by k_scan each launch
__device__ ull sorted_key[ROWS];         // (idx << 32) | row

// ---------------------------------------------------------------- 1) histogram
__global__ __launch_bounds__(1024)
void k_hist(const int4* __restrict__ x4) {
    __shared__ int h[NBUCKETS];
    if (threadIdx.x < NBUCKETS) h[threadIdx.x] = 0;
    __syncthreads();

    int4 v = x4[blockIdx.x * 1024 + threadIdx.x];   // 4 indices, coalesced 16B
    atomicAdd(&h[v.x >> BUCKET_SHIFT], 1);
    atomicAdd(&h[v.y >> BUCKET_SHIFT], 1);
    atomicAdd(&h[v.z >> BUCKET_SHIFT], 1);
    atomicAdd(&h[v.w >> BUCKET_SHIFT], 1);
    __syncthreads();

    if (threadIdx.x < NBUCKETS && h[threadIdx.x])
        atomicAdd(&bucket_total[threadIdx.x], h[threadIdx.x]);
}

// ------------------------------- 2) scan totals -> cursor bases (+ replay reset)
__global__ __launch_bounds__(NBUCKETS)
void k_scan() {
    __shared__ int tmp[NBUCKETS];
    int t = threadIdx.x;
    int v = bucket_total[t];
    tmp[t] = v;
    __syncthreads();
    #pragma unroll
    for (int off = 1; off < NBUCKETS; off <<= 1) {
        int u = (t >= off) ? tmp[t - off] : 0;
        __syncthreads();
        tmp[t] += u;
        __syncthreads();
    }
    bucket_cursor[t] = tmp[t] - v;   // exclusive base (cursor starts at BASE)
    bucket_total[t]  = 0;            // ready for next graph replay
}

// ------------------------- 3) fused re-hist + reserve + rank + direct scatter
__global__ __launch_bounds__(1024)
void k_bin(const int4* __restrict__ x4) {
    __shared__ int h[NBUCKETS];       // block-local counts (pass 1)
    __shared__ int h2[NBUCKETS];      // rank counters (pass 2)
    __shared__ int gbase[NBUCKETS];   // reserved global base per bucket

    int t = threadIdx.x;
    if (t < NBUCKETS) { h[t] = 0; h2[t] = 0; }
    __syncthreads();

    int4 v = x4[blockIdx.x * 1024 + t];
    int b0 = v.x >> BUCKET_SHIFT;
    int b1 = v.y >> BUCKET_SHIFT;
    int b2 = v.z >> BUCKET_SHIFT;
    int b3 = v.w >> BUCKET_SHIFT;
    atomicAdd(&h[b0], 1);
    atomicAdd(&h[b1], 1);
    atomicAdd(&h[b2], 1);
    atomicAdd(&h[b3], 1);
    __syncthreads();

    // reserve a contiguous global range per non-empty bucket
    if (t < NBUCKETS) {
        int c = h[t];
        if (c > 0) gbase[t] = atomicAdd(&bucket_cursor[t], c);
    }
    __syncthreads();

    // rank + direct write into reserved runs (avg 64 keys = 512B contiguous)
    unsigned r = (unsigned)(blockIdx.x * RPB + 4 * t);
    int lr0 = atomicAdd(&h2[b0], 1);
    sorted_key[gbase[b0] + lr0] = ((ull)(unsigned)v.x << 32) | (r + 0u);
    int lr1 = atomicAdd(&h2[b1], 1);
    sorted_key[gbase[b1] + lr1] = ((ull)(unsigned)v.y << 32) | (r + 1u);
    int lr2 = atomicAdd(&h2[b2], 1);
    sorted_key[gbase[b2] + lr2] = ((ull)(unsigned)v.z << 32) | (r + 2u);
    int lr3 = atomicAdd(&h2[b3], 1);
    sorted_key[gbase[b3] + lr3] = ((ull)(unsigned)v.w << 32) | (r + 3u);
}

// ---------------------------------------------------------------- 4) gather
__device__ __forceinline__ float soft_thresh(float v, float sv) {
    float t = __fdividef(1.0f, 1.0f + __expf(-sv));
    float m = fmaxf(fabsf(v) - t, 0.0f);
    return copysignf(m, v);
}

__device__ __forceinline__ float4 soft_thresh4(float4 v, float4 t) {
    float4 o;
    o.x = soft_thresh(v.x, t.x);
    o.y = soft_thresh(v.y, t.y);
    o.z = soft_thresh(v.z, t.z);
    o.w = soft_thresh(v.w, t.w);
    return o;
}

__global__ __launch_bounds__(256, 8)
void k_gather(const float4* __restrict__ emb,
              const float4* __restrict__ s,
              float4* __restrict__ out) {
    // one warp = TWO consecutive sorted rows -> 4 independent loads per thread
    unsigned gid  = blockIdx.x * 256u + threadIdx.x;
    unsigned warp = gid >> 5;
    unsigned comp = gid & 31u;

    ulonglong2 kk = __ldg((const ulonglong2*)&sorted_key[warp * 2]); // uniform
    unsigned row0 = (unsigned)(kk.x & 0xffffffffu);
    unsigned idx0 = (unsigned)(kk.x >> 32);
    unsigned row1 = (unsigned)(kk.y & 0xffffffffu);
    unsigned idx1 = (unsigned)(kk.y >> 32);

    unsigned off0 = idx0 * (unsigned)VEC_PER_ROW + comp;
    unsigned off1 = idx1 * (unsigned)VEC_PER_ROW + comp;

    // 4 independent 16B loads in flight (MLP=4 — measured sweet spot)
    float4 v0 = __ldg(&emb[off0]);
    float4 t0 = __ldg(&s[off0]);
    float4 v1 = __ldg(&emb[off1]);
    float4 t1 = __ldg(&s[off1]);

    __stcs(&out[row0 * (unsigned)VEC_PER_ROW + comp], soft_thresh4(v0, t0));
    __stcs(&out[row1 * (unsigned)VEC_PER_ROW + comp], soft_thresh4(v1, t1));
}

// ---------------------------------------------------------------- launch
extern "C" void kernel_launch(void* const* d_in, const int* in_sizes, int n_in,
                              void* d_out, int out_size) {
    const int4*   x4  = (const int4*)d_in[0];
    const float4* emb = (const float4*)d_in[1];
    const float4* s   = (const float4*)d_in[2];
    float4*       out = (float4*)d_out;

    k_hist<<<NBLK, 1024>>>(x4);
    k_scan<<<1, NBUCKETS>>>();
    k_bin <<<NBLK, 1024>>>(x4);

    // ROWS/2 warps, 8 warps per 256-thread block
    k_gather<<<ROWS / 16, 256>>>(emb, s, out);
}